// round 5
// baseline (speedup 1.0000x reference)
#include <cuda_runtime.h>
#include <cuda_bf16.h>
#include <cstdint>

#define DEVFN __device__ __forceinline__

constexpr int NROWS  = 8192;
constexpr int DDIM   = 256;
constexpr int MT     = 128;          // tile size (rows and cols)
constexpr int NTILES = NROWS / MT;   // 64 column tiles
constexpr float SQRT_SCALE = 1.6986436005760748f;  // sqrt(2*log2(e)), tau=0.5
constexpr float LN2F = 0.6931471805599453f;

// Scratch (device globals; no runtime allocation allowed)
__device__ __align__(16) uint8_t Z1g[NROWS * DDIM];   // int8 quantized unit rows
__device__ __align__(16) uint8_t Z2g[NROWS * DDIM];
__device__ __align__(16) float S1g[NROWS];  // per-row dequant scale (log2-domain folded)
__device__ __align__(16) float S2g[NROWS];
__device__ float RSg[4][NROWS];   // row sums of exp for S11, S22, S12, S21
__device__ float DGg[3][NROWS];   // log2-domain diagonals

// ---------------- helpers ----------------
DEVFN uint32_t smem_u32(const void* p) {
    return (uint32_t)__cvta_generic_to_shared(p);
}
DEVFN void cp_commit() { asm volatile("cp.async.commit_group;" ::: "memory"); }
DEVFN void cp_wait0()  { asm volatile("cp.async.wait_group 0;" ::: "memory"); }

DEVFN float fexp2(float x) {
    float y;
    asm("ex2.approx.ftz.f32 %0, %1;" : "=f"(y) : "f"(x));
    return y;
}

DEVFN void ldm4(uint32_t& r0, uint32_t& r1, uint32_t& r2, uint32_t& r3, uint32_t addr) {
    asm volatile("ldmatrix.sync.aligned.m8n8.x4.shared.b16 {%0,%1,%2,%3}, [%4];"
                 : "=r"(r0), "=r"(r1), "=r"(r2), "=r"(r3) : "r"(addr));
}

// int8 IMMA: D(16x8,s32) += A(16x32,s8) * B(8x32,s8)^T
DEVFN void mma_s8(int* c, const uint32_t* a, uint32_t b0, uint32_t b1) {
    asm volatile(
        "mma.sync.aligned.m16n8k32.row.col.s32.s8.s8.s32 "
        "{%0,%1,%2,%3}, {%4,%5,%6,%7}, {%8,%9}, {%0,%1,%2,%3};"
        : "+r"(c[0]), "+r"(c[1]), "+r"(c[2]), "+r"(c[3])
        : "r"(a[0]), "r"(a[1]), "r"(a[2]), "r"(a[3]), "r"(b0), "r"(b1));
}

DEVFN uint32_t pack4(float a, float b, float c, float d, float s) {
    int ia = __float2int_rn(a * s), ib = __float2int_rn(b * s);
    int ic = __float2int_rn(c * s), id = __float2int_rn(d * s);
    return (uint32_t)((ia & 0xFF) | ((ib & 0xFF) << 8) | ((ic & 0xFF) << 16) | (id << 24));
}

// ---------------- SMEM layout ----------------
constexpr int SM_A     = 0;
constexpr int SM_B0    = SM_A  + 32768;
constexpr int SM_B1    = SM_B0 + 32768;
constexpr int SM_CS0   = SM_B1 + 32768;   // col scales tile buf 0 (512B)
constexpr int SM_CS1   = SM_CS0 + 512;
constexpr int SM_TOTAL = SM_CS1 + 512;    // 99328 B

// swizzled byte offset of (row, 16B-chunk) within a 128x256B int8 tile (16 chunks/row)
DEVFN uint32_t tile_off(int row, int chunk) {
    return (uint32_t)(row * 256 + ((((chunk & 7) ^ (row & 7))) << 4) + ((chunk & 8) << 4));
}

// Load a 128x256B int8 tile into swizzled SMEM via cp.async (16B chunks), 512 threads
DEVFN void load_tile(uint32_t sdst, const uint8_t* __restrict__ src, int tid) {
    #pragma unroll
    for (int it = 0; it < 4; ++it) {
        int idx = tid + it * 512;           // 2048 chunks total
        int row = idx >> 4;                 // 0..127
        int c   = idx & 15;                 // chunk within row
        const uint8_t* gp = src + ((size_t)row << 8) + (c << 4);
        asm volatile("cp.async.cg.shared.global [%0], [%1], 16;"
                     :: "r"(sdst + tile_off(row, c)), "l"(gp) : "memory");
    }
}

// ---------------- Kernel 1: normalize + int8 quantize + diagonals + RS zero ----------------
__global__ void __launch_bounds__(256) norm_kernel(const float* __restrict__ H1,
                                                   const float* __restrict__ H2) {
    // zero RSg (accumulated via atomics by gram_kernel each replay)
    if (blockIdx.x < 128) ((float*)RSg)[blockIdx.x * 256 + threadIdx.x] = 0.f;

    int row  = (blockIdx.x * 256 + threadIdx.x) >> 5;   // one row per warp
    int lane = threadIdx.x & 31;
    const float4* p1 = (const float4*)(H1 + (size_t)row * DDIM);
    const float4* p2 = (const float4*)(H2 + (size_t)row * DDIM);
    float4 x0 = p1[lane], x1 = p1[lane + 32];
    float4 y0 = p2[lane], y1 = p2[lane + 32];

    float ss1 = x0.x*x0.x + x0.y*x0.y + x0.z*x0.z + x0.w*x0.w
              + x1.x*x1.x + x1.y*x1.y + x1.z*x1.z + x1.w*x1.w;
    float ss2 = y0.x*y0.x + y0.y*y0.y + y0.z*y0.z + y0.w*y0.w
              + y1.x*y1.x + y1.y*y1.y + y1.z*y1.z + y1.w*y1.w;
    float mm1 = fmaxf(fmaxf(fmaxf(fabsf(x0.x), fabsf(x0.y)), fmaxf(fabsf(x0.z), fabsf(x0.w))),
                      fmaxf(fmaxf(fabsf(x1.x), fabsf(x1.y)), fmaxf(fabsf(x1.z), fabsf(x1.w))));
    float mm2 = fmaxf(fmaxf(fmaxf(fabsf(y0.x), fabsf(y0.y)), fmaxf(fabsf(y0.z), fabsf(y0.w))),
                      fmaxf(fmaxf(fabsf(y1.x), fabsf(y1.y)), fmaxf(fabsf(y1.z), fabsf(y1.w))));
    #pragma unroll
    for (int o = 16; o; o >>= 1) {
        ss1 += __shfl_xor_sync(0xFFFFFFFFu, ss1, o);
        ss2 += __shfl_xor_sync(0xFFFFFFFFu, ss2, o);
        mm1 = fmaxf(mm1, __shfl_xor_sync(0xFFFFFFFFu, mm1, o));
        mm2 = fmaxf(mm2, __shfl_xor_sync(0xFFFFFFFFu, mm2, o));
    }
    float n1 = fmaxf(sqrtf(ss1), 1e-12f);
    float n2 = fmaxf(sqrtf(ss2), 1e-12f);
    // quantization step: q = round(x * qs), qs = 127 * ||x||^-1 / m  (m = max|z|)
    float m1 = fmaxf(mm1 / n1, 1e-12f);
    float m2 = fmaxf(mm2 / n2, 1e-12f);
    float qs1 = 127.f / (m1 * n1);
    float qs2 = 127.f / (m2 * n2);

    uint32_t q10 = pack4(x0.x, x0.y, x0.z, x0.w, qs1);
    uint32_t q11 = pack4(x1.x, x1.y, x1.z, x1.w, qs1);
    uint32_t q20 = pack4(y0.x, y0.y, y0.z, y0.w, qs2);
    uint32_t q21 = pack4(y1.x, y1.y, y1.z, y1.w, qs2);
    uint32_t* z1 = (uint32_t*)(Z1g + (size_t)row * DDIM);
    uint32_t* z2 = (uint32_t*)(Z2g + (size_t)row * DDIM);
    z1[lane] = q10; z1[lane + 32] = q11;
    z2[lane] = q20; z2[lane + 32] = q21;

    // exact int diagonals from the quantized values
    int d11 = __dp4a((int)q10, (int)q10, __dp4a((int)q11, (int)q11, 0));
    int d22 = __dp4a((int)q20, (int)q20, __dp4a((int)q21, (int)q21, 0));
    int d12 = __dp4a((int)q10, (int)q20, __dp4a((int)q11, (int)q21, 0));
    #pragma unroll
    for (int o = 16; o; o >>= 1) {
        d11 += __shfl_xor_sync(0xFFFFFFFFu, d11, o);
        d22 += __shfl_xor_sync(0xFFFFFFFFu, d22, o);
        d12 += __shfl_xor_sync(0xFFFFFFFFu, d12, o);
    }
    // per-row log2-domain dequant scale: r = sqrt(2*log2 e) * m / 127
    float r1 = SQRT_SCALE * m1 * (1.f / 127.f);
    float r2 = SQRT_SCALE * m2 * (1.f / 127.f);
    if (lane == 0) {
        S1g[row] = r1;
        S2g[row] = r2;
        DGg[0][row] = (float)d11 * r1 * r1;
        DGg[1][row] = (float)d22 * r2 * r2;
        DGg[2][row] = (float)d12 * r1 * r2;
    }
}

// ---------------- Kernel 2: fused Gram row/col-sums of exp with symmetry (int8) ----------------
// 128 CTAs:
//   bx in [0,32):   S11 symmetric, pairs row blocks (p, 63-p), tiles j >= rb
//   bx in [32,64):  S22 symmetric, same pairing
//   bx in [64,128): S12 full, rb = bx-64, row sums -> RSg[2], col sums -> RSg[3]
// 16 warps: wm = wid&3 (32-row slice), wn = wid>>2 (32-col slice). Warp tile 32x32.
__global__ void __launch_bounds__(512, 1) gram_kernel() {
    extern __shared__ char smem[];
    const uint32_t sb = smem_u32(smem);
    const int tid  = threadIdx.x;
    const int wid  = tid >> 5;
    const int lane = tid & 31;
    const int wm = wid & 3;
    const int wn = wid >> 2;
    const int bx = blockIdx.x;

    const uint8_t *X, *Y;
    const float *XS, *YS;
    int mrow, mcol, seg0, seg1, nseg;
    bool sym;
    if (bx < 64) {
        int p = bx & 31;
        bool s22 = (bx >= 32);
        X = Y = s22 ? Z2g : Z1g;
        XS = YS = s22 ? S2g : S1g;
        mrow = mcol = s22 ? 1 : 0;
        seg0 = p; seg1 = 63 - p; nseg = 2; sym = true;
    } else {
        X = Z1g; Y = Z2g;
        XS = S1g; YS = S2g;
        mrow = 2; mcol = 3;
        seg0 = bx - 64; seg1 = 0; nseg = 1; sym = false;
    }

    // ldmatrix lane address components (constant per thread)
    const int l7   = lane & 7;
    const int qA_r = (lane >> 3) & 1;
    const int qA_c = (lane >> 4);
    const int qB_r = (lane >> 4);
    const int qB_c = (lane >> 3) & 1;
    const int l3   = lane & 3;
    const int g    = lane >> 2;

    for (int s = 0; s < nseg; ++s) {
        const int rb = s ? seg1 : seg0;
        const int jstart = sym ? rb : 0;

        // per-thread row dequant scales (rows wm*32 + 8r + g)
        float rsA[4];
        #pragma unroll
        for (int r = 0; r < 4; ++r) rsA[r] = XS[rb * MT + wm * 32 + 8 * r + g];

        load_tile(sb + SM_A, X + (size_t)rb * MT * DDIM, tid);
        load_tile(sb + ((jstart & 1) ? SM_B1 : SM_B0), Y + (size_t)jstart * MT * DDIM, tid);
        if (tid < 32)
            asm volatile("cp.async.cg.shared.global [%0], [%1], 16;"
                         :: "r"(sb + ((jstart & 1) ? SM_CS1 : SM_CS0) + tid * 16),
                            "l"((const char*)(YS + jstart * MT) + tid * 16) : "memory");
        cp_commit(); cp_wait0();
        __syncthreads();

        float rs[4] = {0.f, 0.f, 0.f, 0.f};

        for (int j = jstart; j < NTILES; ++j) {
            const uint32_t bsm = sb + ((j & 1) ? SM_B1 : SM_B0);

            // col dequant scales for this tile (cols wn*32 + ns*8 + 2*l3 + {0,1})
            float csB[8];
            {
                const float* cs = (const float*)(smem + ((j & 1) ? SM_CS1 : SM_CS0));
                #pragma unroll
                for (int ns = 0; ns < 4; ++ns) {
                    csB[2 * ns]     = cs[wn * 32 + ns * 8 + 2 * l3];
                    csB[2 * ns + 1] = cs[wn * 32 + ns * 8 + 2 * l3 + 1];
                }
            }

            if (j + 1 < NTILES) {
                const int nb = (j + 1) & 1;
                load_tile(sb + (nb ? SM_B1 : SM_B0), Y + (size_t)(j + 1) * MT * DDIM, tid);
                if (tid < 32)
                    asm volatile("cp.async.cg.shared.global [%0], [%1], 16;"
                                 :: "r"(sb + (nb ? SM_CS1 : SM_CS0) + tid * 16),
                                    "l"((const char*)(YS + (j + 1) * MT) + tid * 16) : "memory");
                cp_commit();
            }

            int acc[2][4][4];
            #pragma unroll
            for (int ms = 0; ms < 2; ++ms)
                #pragma unroll
                for (int ns = 0; ns < 4; ++ns)
                    #pragma unroll
                    for (int c = 0; c < 4; ++c) acc[ms][ns][c] = 0;

            #pragma unroll
            for (int ks = 0; ks < 8; ++ks) {
                const int ch = 2 * ks;
                uint32_t a0[4], a1[4];
                {
                    int row = wm * 32 + l7 + 8 * qA_r;
                    ldm4(a0[0], a0[1], a0[2], a0[3], sb + SM_A + tile_off(row,      ch + qA_c));
                    ldm4(a1[0], a1[1], a1[2], a1[3], sb + SM_A + tile_off(row + 16, ch + qA_c));
                }
                uint32_t bf[2][4];
                #pragma unroll
                for (int np = 0; np < 2; ++np) {
                    int row = wn * 32 + np * 16 + l7 + 8 * qB_r;
                    ldm4(bf[np][0], bf[np][1], bf[np][2], bf[np][3],
                         bsm + tile_off(row, ch + qB_c));
                }
                #pragma unroll
                for (int np = 0; np < 2; ++np) {
                    #pragma unroll
                    for (int sub = 0; sub < 2; ++sub) {
                        mma_s8(acc[0][2 * np + sub], a0, bf[np][2 * sub], bf[np][2 * sub + 1]);
                        mma_s8(acc[1][2 * np + sub], a1, bf[np][2 * sub], bf[np][2 * sub + 1]);
                    }
                }
            }

            // epilogue: dequant + exp2, accumulate row sums (registers) and col sums
            float col[8];
            #pragma unroll
            for (int k = 0; k < 8; ++k) col[k] = 0.f;
            #pragma unroll
            for (int ms = 0; ms < 2; ++ms)
                #pragma unroll
                for (int ns = 0; ns < 4; ++ns) {
                    float e0 = fexp2((float)acc[ms][ns][0] * rsA[2 * ms]     * csB[2 * ns]);
                    float e1 = fexp2((float)acc[ms][ns][1] * rsA[2 * ms]     * csB[2 * ns + 1]);
                    float e2 = fexp2((float)acc[ms][ns][2] * rsA[2 * ms + 1] * csB[2 * ns]);
                    float e3 = fexp2((float)acc[ms][ns][3] * rsA[2 * ms + 1] * csB[2 * ns + 1]);
                    rs[2 * ms]     += e0 + e1;
                    rs[2 * ms + 1] += e2 + e3;
                    col[2 * ns]     += e0 + e2;
                    col[2 * ns + 1] += e1 + e3;
                }

            const bool do_col = (!sym) || (j != rb);
            if (do_col) {
                #pragma unroll
                for (int k = 0; k < 8; ++k) {
                    col[k] += __shfl_xor_sync(0xFFFFFFFFu, col[k], 4);
                    col[k] += __shfl_xor_sync(0xFFFFFFFFu, col[k], 8);
                    col[k] += __shfl_xor_sync(0xFFFFFFFFu, col[k], 16);
                }
                if (lane < 4) {
                    float* dst = &RSg[mcol][j * MT + wn * 32];
                    #pragma unroll
                    for (int ns = 0; ns < 4; ++ns) {
                        atomicAdd(dst + ns * 8 + 2 * lane,     col[2 * ns]);
                        atomicAdd(dst + ns * 8 + 2 * lane + 1, col[2 * ns + 1]);
                    }
                }
            }

            if (j + 1 < NTILES) cp_wait0();
            __syncthreads();
        }

        // flush row sums for this segment
        #pragma unroll
        for (int r = 0; r < 4; ++r) {
            rs[r] += __shfl_xor_sync(0xFFFFFFFFu, rs[r], 1);
            rs[r] += __shfl_xor_sync(0xFFFFFFFFu, rs[r], 2);
        }
        if (l3 == 0) {
            float* dst = &RSg[mrow][rb * MT + wm * 32];
            #pragma unroll
            for (int ms = 0; ms < 2; ++ms)
                #pragma unroll
                for (int cc = 0; cc < 2; ++cc)
                    atomicAdd(dst + ms * 16 + 8 * cc + g, rs[2 * ms + cc]);
        }
        __syncthreads();  // before next segment overwrites A
    }
}

// ---------------- Kernel 3: final reduction ----------------
__global__ void __launch_bounds__(256) reduce_kernel(float* out) {
    float s = 0.f;
    for (int i = threadIdx.x; i < NROWS; i += 256) {
        float den1 = RSg[0][i] + RSg[2][i] - exp2f(DGg[0][i]);
        float den2 = RSg[1][i] + RSg[3][i] - exp2f(DGg[1][i]);
        s += 0.5f * (__logf(den1) + __logf(den2)) - DGg[2][i] * LN2F;
    }
    #pragma unroll
    for (int o = 16; o; o >>= 1) s += __shfl_xor_sync(0xFFFFFFFFu, s, o);
    __shared__ float ws[8];
    if ((threadIdx.x & 31) == 0) ws[threadIdx.x >> 5] = s;
    __syncthreads();
    if (threadIdx.x < 8) {
        s = ws[threadIdx.x];
        #pragma unroll
        for (int o = 4; o; o >>= 1) s += __shfl_xor_sync(0xFFu, s, o);
        if (threadIdx.x == 0) out[0] = s / (float)NROWS;
    }
}

// ---------------- launch ----------------
extern "C" void kernel_launch(void* const* d_in, const int* in_sizes, int n_in,
                              void* d_out, int out_size) {
    const float* H1 = (const float*)d_in[0];
    const float* H2 = (const float*)d_in[1];
    float* out = (float*)d_out;

    norm_kernel<<<NROWS * 32 / 256, 256>>>(H1, H2);

    static bool attr_set = false;
    if (!attr_set) {
        cudaFuncSetAttribute(gram_kernel, cudaFuncAttributeMaxDynamicSharedMemorySize, SM_TOTAL);
        attr_set = true;
    }
    gram_kernel<<<128, 512, SM_TOTAL>>>();

    reduce_kernel<<<1, 256>>>(out);
}

// round 6
// speedup vs baseline: 2.8500x; 2.8500x over previous
#include <cuda_runtime.h>
#include <cuda_bf16.h>
#include <cstdint>

#define DEVFN __device__ __forceinline__

constexpr int NROWS  = 8192;
constexpr int DDIM   = 256;
constexpr int MT     = 128;          // tile size (rows and cols)
constexpr int NTILES = NROWS / MT;   // 64 column tiles
constexpr int NCTA   = 148;
constexpr int JOBS_SYM = NTILES * (NTILES + 1) / 2;          // 2080
constexpr int JOBS_ALL = 2 * JOBS_SYM + NTILES * NTILES;     // 8256
// exp(s/tau) = exp2(s * 2*log2(e)); fold sqrt of that into each operand
constexpr float SQRT_SCALE = 1.6986436005760748f;  // sqrt(2*log2(e)), tau=0.5
constexpr float LN2F = 0.6931471805599453f;

// Scratch (device globals; no runtime allocation allowed)
__device__ __align__(16) __nv_bfloat16 Z1g[NROWS * DDIM];
__device__ __align__(16) __nv_bfloat16 Z2g[NROWS * DDIM];
__device__ float RSg[4][NROWS];   // row sums of exp for S11, S22, S12, S21
__device__ float DGg[3][NROWS];   // log2-domain diagonals

// ---------------- helpers ----------------
DEVFN uint32_t smem_u32(const void* p) {
    return (uint32_t)__cvta_generic_to_shared(p);
}
DEVFN void cp_commit() { asm volatile("cp.async.commit_group;" ::: "memory"); }
DEVFN void cp_wait0()  { asm volatile("cp.async.wait_group 0;" ::: "memory"); }
DEVFN void cp_wait1()  { asm volatile("cp.async.wait_group 1;" ::: "memory"); }

DEVFN float fexp2(float x) {
    float y;
    asm("ex2.approx.ftz.f32 %0, %1;" : "=f"(y) : "f"(x));
    return y;
}

DEVFN void ldm4(uint32_t& r0, uint32_t& r1, uint32_t& r2, uint32_t& r3, uint32_t addr) {
    asm volatile("ldmatrix.sync.aligned.m8n8.x4.shared.b16 {%0,%1,%2,%3}, [%4];"
                 : "=r"(r0), "=r"(r1), "=r"(r2), "=r"(r3) : "r"(addr));
}

DEVFN void mma_bf16(float* c, const uint32_t* a, uint32_t b0, uint32_t b1) {
    asm volatile(
        "mma.sync.aligned.m16n8k16.row.col.f32.bf16.bf16.f32 "
        "{%0,%1,%2,%3}, {%4,%5,%6,%7}, {%8,%9}, {%0,%1,%2,%3};"
        : "+f"(c[0]), "+f"(c[1]), "+f"(c[2]), "+f"(c[3])
        : "r"(a[0]), "r"(a[1]), "r"(a[2]), "r"(a[3]), "r"(b0), "r"(b1));
}

// ---------------- SMEM layout ----------------
constexpr int SM_A     = 0;
constexpr int SM_B0    = SM_A  + 65536;
constexpr int SM_B1    = SM_B0 + 65536;
constexpr int SM_TOTAL = SM_B1 + 65536;   // 196608 B

// swizzled byte offset of (row, 16B-chunk) within a 128x256 bf16 tile
DEVFN uint32_t tile_off(int row, int chunk) {
    return (uint32_t)(row * 512 + ((((chunk & 7) ^ (row & 7))) << 4) + ((chunk & 24) << 4));
}

// Load a 128x256 bf16 tile into swizzled SMEM via cp.async (16B chunks), 512 threads
DEVFN void load_tile(uint32_t sdst, const __nv_bfloat16* __restrict__ src, int tid) {
    #pragma unroll
    for (int it = 0; it < 8; ++it) {
        int idx = tid + it * 512;           // 4096 chunks total
        int row = idx >> 5;                 // 0..127
        int c   = idx & 31;                 // chunk within row
        const __nv_bfloat16* gp = src + ((size_t)row << 8) + (c << 3);
        asm volatile("cp.async.cg.shared.global [%0], [%1], 16;"
                     :: "r"(sdst + tile_off(row, c)), "l"(gp) : "memory");
    }
}

// Compute one 128x128 tile into acc; optionally interleave the exp-epilogue of
// the previous tile's accumulators (prev) into the k-loop so MUFU overlaps HMMA.
template<bool HAVE_PREV>
DEVFN void compute_tile(float (&acc)[2][4][4], float (&prev)[2][4][4],
                        float (&rs)[4], float (&col)[8],
                        uint32_t sbA, uint32_t bsm,
                        int wm, int wn, int l7,
                        int qA_r, int qA_c, int qB_r, int qB_c) {
    #pragma unroll
    for (int ms = 0; ms < 2; ++ms)
        #pragma unroll
        for (int ns = 0; ns < 4; ++ns)
            #pragma unroll
            for (int c = 0; c < 4; ++c) acc[ms][ns][c] = 0.f;
    if (HAVE_PREV) {
        #pragma unroll
        for (int k = 0; k < 8; ++k) col[k] = 0.f;
    }
    #pragma unroll
    for (int ks = 0; ks < 16; ++ks) {
        const int ch = 2 * ks;
        uint32_t a0[4], a1[4];
        {
            int row = wm * 32 + l7 + 8 * qA_r;
            ldm4(a0[0], a0[1], a0[2], a0[3], sbA + tile_off(row,      ch + qA_c));
            ldm4(a1[0], a1[1], a1[2], a1[3], sbA + tile_off(row + 16, ch + qA_c));
        }
        uint32_t bf[2][4];
        #pragma unroll
        for (int np = 0; np < 2; ++np) {
            int row = wn * 32 + np * 16 + l7 + 8 * qB_r;
            ldm4(bf[np][0], bf[np][1], bf[np][2], bf[np][3],
                 bsm + tile_off(row, ch + qB_c));
        }
        #pragma unroll
        for (int np = 0; np < 2; ++np)
            #pragma unroll
            for (int sub = 0; sub < 2; ++sub) {
                mma_bf16(acc[0][2 * np + sub], a0, bf[np][2 * sub], bf[np][2 * sub + 1]);
                mma_bf16(acc[1][2 * np + sub], a1, bf[np][2 * sub], bf[np][2 * sub + 1]);
            }
        if (HAVE_PREV) {
            #pragma unroll
            for (int t = 0; t < 2; ++t) {
                const int e  = 2 * ks + t;
                const int ms = e >> 4, ns = (e >> 2) & 3, c = e & 3;
                float v = fexp2(prev[ms][ns][c]);
                rs[2 * ms + (c >> 1)] += v;
                col[2 * ns + (c & 1)] += v;
            }
        }
    }
}

DEVFN void epilogue_tail(float (&prev)[2][4][4], float (&rs)[4], float (&col)[8]) {
    #pragma unroll
    for (int k = 0; k < 8; ++k) col[k] = 0.f;
    #pragma unroll
    for (int e = 0; e < 32; ++e) {
        const int ms = e >> 4, ns = (e >> 2) & 3, c = e & 3;
        float v = fexp2(prev[ms][ns][c]);
        rs[2 * ms + (c >> 1)] += v;
        col[2 * ns + (c & 1)] += v;
    }
}

DEVFN void flush_col(float (&col)[8], int mcol, int jprev, int wn, int lane) {
    #pragma unroll
    for (int k = 0; k < 8; ++k) {
        col[k] += __shfl_xor_sync(0xFFFFFFFFu, col[k], 4);
        col[k] += __shfl_xor_sync(0xFFFFFFFFu, col[k], 8);
        col[k] += __shfl_xor_sync(0xFFFFFFFFu, col[k], 16);
    }
    if (lane < 4) {
        float* dst = &RSg[mcol][jprev * MT + wn * 32];
        #pragma unroll
        for (int ns = 0; ns < 4; ++ns) {
            atomicAdd(dst + ns * 8 + 2 * lane,     col[2 * ns]);
            atomicAdd(dst + ns * 8 + 2 * lane + 1, col[2 * ns + 1]);
        }
    }
}

// ---------------- Kernel 1: normalize (pre-scaled) + diagonals + RS zero ----------------
__global__ void __launch_bounds__(256) norm_kernel(const float* __restrict__ H1,
                                                   const float* __restrict__ H2) {
    if (blockIdx.x < 128) ((float*)RSg)[blockIdx.x * 256 + threadIdx.x] = 0.f;

    int row  = (blockIdx.x * 256 + threadIdx.x) >> 5;   // one row per warp
    int lane = threadIdx.x & 31;
    const float4* p1 = (const float4*)(H1 + (size_t)row * DDIM);
    const float4* p2 = (const float4*)(H2 + (size_t)row * DDIM);
    float4 x0 = p1[lane], x1 = p1[lane + 32];
    float4 y0 = p2[lane], y1 = p2[lane + 32];

    float ss1 = x0.x*x0.x + x0.y*x0.y + x0.z*x0.z + x0.w*x0.w
              + x1.x*x1.x + x1.y*x1.y + x1.z*x1.z + x1.w*x1.w;
    float ss2 = y0.x*y0.x + y0.y*y0.y + y0.z*y0.z + y0.w*y0.w
              + y1.x*y1.x + y1.y*y1.y + y1.z*y1.z + y1.w*y1.w;
    #pragma unroll
    for (int o = 16; o; o >>= 1) {
        ss1 += __shfl_xor_sync(0xFFFFFFFFu, ss1, o);
        ss2 += __shfl_xor_sync(0xFFFFFFFFu, ss2, o);
    }
    float inv1 = SQRT_SCALE / fmaxf(sqrtf(ss1), 1e-12f);
    float inv2 = SQRT_SCALE / fmaxf(sqrtf(ss2), 1e-12f);

    __nv_bfloat162 z1p[4], z2p[4];
    z1p[0] = __float22bfloat162_rn(make_float2(x0.x * inv1, x0.y * inv1));
    z1p[1] = __float22bfloat162_rn(make_float2(x0.z * inv1, x0.w * inv1));
    z1p[2] = __float22bfloat162_rn(make_float2(x1.x * inv1, x1.y * inv1));
    z1p[3] = __float22bfloat162_rn(make_float2(x1.z * inv1, x1.w * inv1));
    z2p[0] = __float22bfloat162_rn(make_float2(y0.x * inv2, y0.y * inv2));
    z2p[1] = __float22bfloat162_rn(make_float2(y0.z * inv2, y0.w * inv2));
    z2p[2] = __float22bfloat162_rn(make_float2(y1.x * inv2, y1.y * inv2));
    z2p[3] = __float22bfloat162_rn(make_float2(y1.z * inv2, y1.w * inv2));

    uint32_t* z1 = (uint32_t*)(Z1g + (size_t)row * DDIM);
    uint32_t* z2 = (uint32_t*)(Z2g + (size_t)row * DDIM);
    z1[2 * lane]          = *(uint32_t*)&z1p[0];
    z1[2 * lane + 1]      = *(uint32_t*)&z1p[1];
    z1[64 + 2 * lane]     = *(uint32_t*)&z1p[2];
    z1[64 + 2 * lane + 1] = *(uint32_t*)&z1p[3];
    z2[2 * lane]          = *(uint32_t*)&z2p[0];
    z2[2 * lane + 1]      = *(uint32_t*)&z2p[1];
    z2[64 + 2 * lane]     = *(uint32_t*)&z2p[2];
    z2[64 + 2 * lane + 1] = *(uint32_t*)&z2p[3];

    float d11 = 0.f, d22 = 0.f, d12 = 0.f;
    #pragma unroll
    for (int k = 0; k < 4; ++k) {
        float2 f1 = __bfloat1622float2(z1p[k]);
        float2 f2 = __bfloat1622float2(z2p[k]);
        d11 += f1.x * f1.x + f1.y * f1.y;
        d22 += f2.x * f2.x + f2.y * f2.y;
        d12 += f1.x * f2.x + f1.y * f2.y;
    }
    #pragma unroll
    for (int o = 16; o; o >>= 1) {
        d11 += __shfl_xor_sync(0xFFFFFFFFu, d11, o);
        d22 += __shfl_xor_sync(0xFFFFFFFFu, d22, o);
        d12 += __shfl_xor_sync(0xFFFFFFFFu, d12, o);
    }
    if (lane == 0) {
        DGg[0][row] = d11;   // log2-domain diagonals
        DGg[1][row] = d22;
        DGg[2][row] = d12;
    }
}

// ---------------- Kernel 2: flattened job schedule over 148 CTAs ----------------
// Job list: [S11 upper-tri 2080][S22 upper-tri 2080][S12 full 4096] = 8256 tiles.
// CTA bx handles jobs [bx*8256/148, (bx+1)*8256/148). Segments = runs of equal
// (mat, rb); A stays in SMEM per segment, B double-buffered, epilogue of tile
// j-1 interleaved into the k-loop of tile j.
__global__ void __launch_bounds__(512, 1) gram_kernel() {
    extern __shared__ char smem[];
    const uint32_t sb = smem_u32(smem);
    const int tid  = threadIdx.x;
    const int wid  = tid >> 5;
    const int lane = tid & 31;
    const int wm = wid & 3;
    const int wn = wid >> 2;
    const int bx = blockIdx.x;

    const int l7   = lane & 7;
    const int qA_r = (lane >> 3) & 1;
    const int qA_c = (lane >> 4);
    const int qB_r = (lane >> 4);
    const int qB_c = (lane >> 3) & 1;
    const int l3   = lane & 3;
    const int g    = lane >> 2;

    const int start = bx * JOBS_ALL / NCTA;
    const int end   = (bx + 1) * JOBS_ALL / NCTA;

    // decode start -> (mat, rb, j)
    int mat, rb, j;
    {
        int idx = start;
        if (idx < JOBS_SYM)          { mat = 0; }
        else if (idx < 2 * JOBS_SYM) { mat = 1; idx -= JOBS_SYM; }
        else                         { mat = 2; idx -= 2 * JOBS_SYM; }
        if (mat < 2) {
            rb = 0;
            while (idx >= NTILES - rb) { idx -= NTILES - rb; ++rb; }
            j = rb + idx;
        } else { rb = idx >> 6; j = idx & 63; }
    }

    int remaining = end - start;
    float acc0[2][4][4], acc1[2][4][4], rs[4], col[8];

    while (remaining > 0) {
        const __nv_bfloat16 *X, *Y;
        int mrow, mcol; bool sym;
        if (mat == 0)      { X = Z1g; Y = Z1g; mrow = 0; mcol = 0; sym = true; }
        else if (mat == 1) { X = Z2g; Y = Z2g; mrow = 1; mcol = 1; sym = true; }
        else               { X = Z1g; Y = Z2g; mrow = 2; mcol = 3; sym = false; }

        const int j0 = j;
        const int seg = min(remaining, NTILES - j0);
        const int jend = j0 + seg;

        __syncthreads();   // previous segment fully done reading A/B
        load_tile(sb + SM_A, X + (size_t)rb * MT * DDIM, tid);
        load_tile(sb + ((j0 & 1) ? SM_B1 : SM_B0), Y + (size_t)j0 * MT * DDIM, tid);
        cp_commit();
        if (j0 + 1 < jend) {
            load_tile(sb + (((j0 + 1) & 1) ? SM_B1 : SM_B0),
                      Y + (size_t)(j0 + 1) * MT * DDIM, tid);
            cp_commit();
        }

        #pragma unroll
        for (int r = 0; r < 4; ++r) rs[r] = 0.f;

        for (int jj = j0; jj < jend; ++jj) {
            if (jj + 1 < jend) cp_wait1(); else cp_wait0();
            __syncthreads();
            const uint32_t bsm = sb + ((jj & 1) ? SM_B1 : SM_B0);
            if (jj == j0) {
                compute_tile<false>(acc0, acc1, rs, col, sb + SM_A, bsm,
                                    wm, wn, l7, qA_r, qA_c, qB_r, qB_c);
            } else if ((jj - j0) & 1) {
                compute_tile<true>(acc1, acc0, rs, col, sb + SM_A, bsm,
                                   wm, wn, l7, qA_r, qA_c, qB_r, qB_c);
            } else {
                compute_tile<true>(acc0, acc1, rs, col, sb + SM_A, bsm,
                                   wm, wn, l7, qA_r, qA_c, qB_r, qB_c);
            }
            if (jj > j0 && (!sym || (jj - 1) != rb))
                flush_col(col, mcol, jj - 1, wn, lane);
            __syncthreads();   // all warps finished reading B(jj)
            if (jj + 2 < jend) {
                load_tile(sb + ((jj & 1) ? SM_B1 : SM_B0),
                          Y + (size_t)(jj + 2) * MT * DDIM, tid);
                cp_commit();
            }
        }

        // tail epilogue for last tile
        if ((jend - 1 - j0) & 1) epilogue_tail(acc1, rs, col);
        else                     epilogue_tail(acc0, rs, col);
        if (!sym || (jend - 1) != rb)
            flush_col(col, mcol, jend - 1, wn, lane);

        // flush row sums for this segment
        #pragma unroll
        for (int r = 0; r < 4; ++r) {
            rs[r] += __shfl_xor_sync(0xFFFFFFFFu, rs[r], 1);
            rs[r] += __shfl_xor_sync(0xFFFFFFFFu, rs[r], 2);
        }
        if (l3 == 0) {
            float* dst = &RSg[mrow][rb * MT + wm * 32];
            #pragma unroll
            for (int ms = 0; ms < 2; ++ms)
                #pragma unroll
                for (int cc = 0; cc < 2; ++cc)
                    atomicAdd(dst + ms * 16 + 8 * cc + g, rs[2 * ms + cc]);
        }

        // advance schedule state
        remaining -= seg;
        j = jend;
        if (j == NTILES) {
            ++rb;
            if (mat < 2) {
                if (rb == NTILES) { ++mat; rb = 0; j = 0; }
                else j = rb;
            } else {
                j = 0;
            }
        }
    }
}

// ---------------- Kernel 3: final reduction ----------------
__global__ void __launch_bounds__(256) reduce_kernel(float* out) {
    float s = 0.f;
    for (int i = threadIdx.x; i < NROWS; i += 256) {
        float den1 = RSg[0][i] + RSg[2][i] - exp2f(DGg[0][i]);
        float den2 = RSg[1][i] + RSg[3][i] - exp2f(DGg[1][i]);
        s += 0.5f * (__logf(den1) + __logf(den2)) - DGg[2][i] * LN2F;
    }
    #pragma unroll
    for (int o = 16; o; o >>= 1) s += __shfl_xor_sync(0xFFFFFFFFu, s, o);
    __shared__ float ws[8];
    if ((threadIdx.x & 31) == 0) ws[threadIdx.x >> 5] = s;
    __syncthreads();
    if (threadIdx.x < 8) {
        s = ws[threadIdx.x];
        #pragma unroll
        for (int o = 4; o; o >>= 1) s += __shfl_xor_sync(0xFFu, s, o);
        if (threadIdx.x == 0) out[0] = s / (float)NROWS;
    }
}

// ---------------- launch ----------------
extern "C" void kernel_launch(void* const* d_in, const int* in_sizes, int n_in,
                              void* d_out, int out_size) {
    const float* H1 = (const float*)d_in[0];
    const float* H2 = (const float*)d_in[1];
    float* out = (float*)d_out;

    norm_kernel<<<NROWS * 32 / 256, 256>>>(H1, H2);

    static bool attr_set = false;
    if (!attr_set) {
        cudaFuncSetAttribute(gram_kernel, cudaFuncAttributeMaxDynamicSharedMemorySize, SM_TOTAL);
        attr_set = true;
    }
    gram_kernel<<<NCTA, 512, SM_TOTAL>>>();

    reduce_kernel<<<1, 256>>>(out);
}

// round 8
// speedup vs baseline: 3.1281x; 1.0976x over previous
#include <cuda_runtime.h>
#include <cuda_bf16.h>
#include <cstdint>

#define DEVFN __device__ __forceinline__

constexpr int NROWS  = 8192;
constexpr int DDIM   = 256;
constexpr int MT     = 128;          // tile size (rows and cols)
constexpr int NTILES = NROWS / MT;   // 64 column tiles
constexpr int NCTA   = 148;
constexpr int JOBS_SYM = NTILES * (NTILES + 1) / 2;          // 2080
constexpr int JOBS_ALL = 2 * JOBS_SYM + NTILES * NTILES;     // 8256
constexpr float SQRT_SCALE = 1.6986436005760748f;  // sqrt(2*log2(e)), tau=0.5
constexpr float LN2F = 0.6931471805599453f;

// Scratch (device globals; no runtime allocation allowed)
__device__ __align__(16) __nv_bfloat16 Z1g[NROWS * DDIM];
__device__ __align__(16) __nv_bfloat16 Z2g[NROWS * DDIM];
__device__ float RSg[4][NROWS];   // row sums of exp for S11, S22, S12, S21
__device__ float DGg[3][NROWS];   // log2-domain diagonals

// ---------------- helpers ----------------
DEVFN uint32_t smem_u32(const void* p) {
    return (uint32_t)__cvta_generic_to_shared(p);
}
DEVFN float fexp2(float x) {
    float y;
    asm("ex2.approx.ftz.f32 %0, %1;" : "=f"(y) : "f"(x));
    return y;
}
DEVFN void ldm4(uint32_t& r0, uint32_t& r1, uint32_t& r2, uint32_t& r3, uint32_t addr) {
    asm volatile("ldmatrix.sync.aligned.m8n8.x4.shared.b16 {%0,%1,%2,%3}, [%4];"
                 : "=r"(r0), "=r"(r1), "=r"(r2), "=r"(r3) : "r"(addr));
}
DEVFN void mma_bf16(float* c, const uint32_t* a, uint32_t b0, uint32_t b1) {
    asm volatile(
        "mma.sync.aligned.m16n8k16.row.col.f32.bf16.bf16.f32 "
        "{%0,%1,%2,%3}, {%4,%5,%6,%7}, {%8,%9}, {%0,%1,%2,%3};"
        : "+f"(c[0]), "+f"(c[1]), "+f"(c[2]), "+f"(c[3])
        : "r"(a[0]), "r"(a[1]), "r"(a[2]), "r"(a[3]), "r"(b0), "r"(b1));
}
// mbarrier primitives (sm_80/90 base features)
DEVFN void mbar_init(uint32_t mbar, uint32_t cnt) {
    asm volatile("mbarrier.init.shared.b64 [%0], %1;" :: "r"(mbar), "r"(cnt) : "memory");
}
DEVFN void mbar_arrive(uint32_t mbar) {
    asm volatile("mbarrier.arrive.shared.b64 _, [%0];" :: "r"(mbar) : "memory");
}
// .noinc: the async arrival decrements the pending count that mbarrier.init
// accounted for (init count includes these arrivals). Without .noinc the op is
// net-zero on the pending count and the barrier never completes -> deadlock.
DEVFN void cp_mbar_arrive_noinc(uint32_t mbar) {
    asm volatile("cp.async.mbarrier.arrive.noinc.shared.b64 [%0];" :: "r"(mbar) : "memory");
}
DEVFN void mbar_wait(uint32_t mbar, uint32_t parity) {
    asm volatile(
        "{\n\t.reg .pred P;\n"
        "MW_%=:\n\t"
        "mbarrier.try_wait.parity.shared.b64 P, [%0], %1;\n\t"
        "@!P bra MW_%=;\n\t}"
        :: "r"(mbar), "r"(parity) : "memory");
}

// ---------------- SMEM layout ----------------
constexpr int SM_MBAR  = 0;      // full0, full1, empty0, empty1 (8B each)
constexpr int SM_A     = 1024;
constexpr int SM_B0    = SM_A  + 65536;
constexpr int SM_B1    = SM_B0 + 65536;
constexpr int SM_TOTAL = SM_B1 + 65536;   // 197632 B

// swizzled byte offset of (row, 16B-chunk) within a 128x256 bf16 tile
DEVFN uint32_t tile_off(int row, int chunk) {
    return (uint32_t)(row * 512 + ((((chunk & 7) ^ (row & 7))) << 4) + ((chunk & 24) << 4));
}

// Load a 128x256 bf16 tile into swizzled SMEM via cp.async (16B chunks), 512 threads
DEVFN void load_tile(uint32_t sdst, const __nv_bfloat16* __restrict__ src, int tid) {
    #pragma unroll
    for (int it = 0; it < 8; ++it) {
        int idx = tid + it * 512;           // 4096 chunks total
        int row = idx >> 5;                 // 0..127
        int c   = idx & 31;                 // chunk within row
        const __nv_bfloat16* gp = src + ((size_t)row << 8) + (c << 3);
        asm volatile("cp.async.cg.shared.global [%0], [%1], 16;"
                     :: "r"(sdst + tile_off(row, c)), "l"(gp) : "memory");
    }
}

// ---------------- Kernel 1: normalize (pre-scaled) + diagonals + RS zero ----------------
__global__ void __launch_bounds__(256) norm_kernel(const float* __restrict__ H1,
                                                   const float* __restrict__ H2) {
    if (blockIdx.x < 128) ((float*)RSg)[blockIdx.x * 256 + threadIdx.x] = 0.f;

    int row  = (blockIdx.x * 256 + threadIdx.x) >> 5;   // one row per warp
    int lane = threadIdx.x & 31;
    const float4* p1 = (const float4*)(H1 + (size_t)row * DDIM);
    const float4* p2 = (const float4*)(H2 + (size_t)row * DDIM);
    float4 x0 = p1[lane], x1 = p1[lane + 32];
    float4 y0 = p2[lane], y1 = p2[lane + 32];

    float ss1 = x0.x*x0.x + x0.y*x0.y + x0.z*x0.z + x0.w*x0.w
              + x1.x*x1.x + x1.y*x1.y + x1.z*x1.z + x1.w*x1.w;
    float ss2 = y0.x*y0.x + y0.y*y0.y + y0.z*y0.z + y0.w*y0.w
              + y1.x*y1.x + y1.y*y1.y + y1.z*y1.z + y1.w*y1.w;
    #pragma unroll
    for (int o = 16; o; o >>= 1) {
        ss1 += __shfl_xor_sync(0xFFFFFFFFu, ss1, o);
        ss2 += __shfl_xor_sync(0xFFFFFFFFu, ss2, o);
    }
    float inv1 = SQRT_SCALE / fmaxf(sqrtf(ss1), 1e-12f);
    float inv2 = SQRT_SCALE / fmaxf(sqrtf(ss2), 1e-12f);

    __nv_bfloat162 z1p[4], z2p[4];
    z1p[0] = __float22bfloat162_rn(make_float2(x0.x * inv1, x0.y * inv1));
    z1p[1] = __float22bfloat162_rn(make_float2(x0.z * inv1, x0.w * inv1));
    z1p[2] = __float22bfloat162_rn(make_float2(x1.x * inv1, x1.y * inv1));
    z1p[3] = __float22bfloat162_rn(make_float2(x1.z * inv1, x1.w * inv1));
    z2p[0] = __float22bfloat162_rn(make_float2(y0.x * inv2, y0.y * inv2));
    z2p[1] = __float22bfloat162_rn(make_float2(y0.z * inv2, y0.w * inv2));
    z2p[2] = __float22bfloat162_rn(make_float2(y1.x * inv2, y1.y * inv2));
    z2p[3] = __float22bfloat162_rn(make_float2(y1.z * inv2, y1.w * inv2));

    uint32_t* z1 = (uint32_t*)(Z1g + (size_t)row * DDIM);
    uint32_t* z2 = (uint32_t*)(Z2g + (size_t)row * DDIM);
    z1[2 * lane]          = *(uint32_t*)&z1p[0];
    z1[2 * lane + 1]      = *(uint32_t*)&z1p[1];
    z1[64 + 2 * lane]     = *(uint32_t*)&z1p[2];
    z1[64 + 2 * lane + 1] = *(uint32_t*)&z1p[3];
    z2[2 * lane]          = *(uint32_t*)&z2p[0];
    z2[2 * lane + 1]      = *(uint32_t*)&z2p[1];
    z2[64 + 2 * lane]     = *(uint32_t*)&z2p[2];
    z2[64 + 2 * lane + 1] = *(uint32_t*)&z2p[3];

    float d11 = 0.f, d22 = 0.f, d12 = 0.f;
    #pragma unroll
    for (int k = 0; k < 4; ++k) {
        float2 f1 = __bfloat1622float2(z1p[k]);
        float2 f2 = __bfloat1622float2(z2p[k]);
        d11 += f1.x * f1.x + f1.y * f1.y;
        d22 += f2.x * f2.x + f2.y * f2.y;
        d12 += f1.x * f2.x + f1.y * f2.y;
    }
    #pragma unroll
    for (int o = 16; o; o >>= 1) {
        d11 += __shfl_xor_sync(0xFFFFFFFFu, d11, o);
        d22 += __shfl_xor_sync(0xFFFFFFFFu, d22, o);
        d12 += __shfl_xor_sync(0xFFFFFFFFu, d12, o);
    }
    if (lane == 0) {
        DGg[0][row] = d11;   // log2-domain diagonals
        DGg[1][row] = d22;
        DGg[2][row] = d12;
    }
}

// ---------------- Kernel 2: flat schedule + mbarrier pipeline (no per-tile CTA barrier) ----
// Job list: [S11 upper-tri 2080][S22 upper-tri 2080][S12 full 4096] = 8256 tiles over 148 CTAs.
// Buffers full[b] (512 noinc cp-arrivals) / empty[b] (16 warp arrivals). Warps run free; a
// warp's exp-epilogue overlaps other warps' HMMA phase.
__global__ void __launch_bounds__(512, 1) gram_kernel() {
    extern __shared__ char smem[];
    const uint32_t sb = smem_u32(smem);
    const int tid  = threadIdx.x;
    const int wid  = tid >> 5;
    const int lane = tid & 31;
    const int wm = wid & 3;
    const int wn = wid >> 2;
    const int bx = blockIdx.x;

    const uint32_t mb_full[2]  = { sb + SM_MBAR,      sb + SM_MBAR + 8 };
    const uint32_t mb_empty[2] = { sb + SM_MBAR + 16, sb + SM_MBAR + 24 };
    if (tid == 0) {
        mbar_init(mb_full[0], 512);
        mbar_init(mb_full[1], 512);
        mbar_init(mb_empty[0], 16);
        mbar_init(mb_empty[1], 16);
    }
    int n_full[2]  = {0, 0};   // loads issued into buffer b (completions of full[b])
    int n_empty[2] = {0, 0};   // tiles consumed from buffer b (completions of empty[b])

    const int l7   = lane & 7;
    const int qA_r = (lane >> 3) & 1;
    const int qA_c = (lane >> 4);
    const int qB_r = (lane >> 4);
    const int qB_c = (lane >> 3) & 1;
    const int l3   = lane & 3;
    const int g    = lane >> 2;

    const int start = bx * JOBS_ALL / NCTA;
    const int end   = (bx + 1) * JOBS_ALL / NCTA;

    // decode start -> (mat, rb, j)
    int mat, rb, j;
    {
        int idx = start;
        if (idx < JOBS_SYM)          { mat = 0; }
        else if (idx < 2 * JOBS_SYM) { mat = 1; idx -= JOBS_SYM; }
        else                         { mat = 2; idx -= 2 * JOBS_SYM; }
        if (mat < 2) {
            rb = 0;
            while (idx >= NTILES - rb) { idx -= NTILES - rb; ++rb; }
            j = rb + idx;
        } else { rb = idx >> 6; j = idx & 63; }
    }

    int remaining = end - start;

    while (remaining > 0) {
        const __nv_bfloat16 *X, *Y;
        int mrow, mcol; bool sym;
        if (mat == 0)      { X = Z1g; Y = Z1g; mrow = 0; mcol = 0; sym = true; }
        else if (mat == 1) { X = Z2g; Y = Z2g; mrow = 1; mcol = 1; sym = true; }
        else               { X = Z1g; Y = Z2g; mrow = 2; mcol = 3; sym = false; }

        const int j0 = j;
        const int seg = min(remaining, NTILES - j0);
        const int jend = j0 + seg;

        // quiesce: all warps done with previous segment's A/B (also orders mbar init)
        __syncthreads();

        // prologue: A + first (up to) two B tiles
        load_tile(sb + SM_A, X + (size_t)rb * MT * DDIM, tid);
        {
            const int b0 = j0 & 1;
            load_tile(b0 ? sb + SM_B1 : sb + SM_B0, Y + (size_t)j0 * MT * DDIM, tid);
            cp_mbar_arrive_noinc(mb_full[b0]);
            ++n_full[b0];
            if (j0 + 1 < jend) {
                const int b1 = b0 ^ 1;
                load_tile(b1 ? sb + SM_B1 : sb + SM_B0, Y + (size_t)(j0 + 1) * MT * DDIM, tid);
                cp_mbar_arrive_noinc(mb_full[b1]);
                ++n_full[b1];
            }
        }

        float rs[4] = {0.f, 0.f, 0.f, 0.f};

        for (int jj = j0; jj < jend; ++jj) {
            const int b = jj & 1;
            const uint32_t bsm = b ? sb + SM_B1 : sb + SM_B0;

            // wait for this tile's data (load #n_full[b] into buffer b)
            mbar_wait(mb_full[b], (uint32_t)((n_full[b] - 1) & 1));

            float acc[2][4][4];
            #pragma unroll
            for (int ms = 0; ms < 2; ++ms)
                #pragma unroll
                for (int ns = 0; ns < 4; ++ns)
                    #pragma unroll
                    for (int c = 0; c < 4; ++c) acc[ms][ns][c] = 0.f;

            #pragma unroll
            for (int ks = 0; ks < 16; ++ks) {
                const int ch = 2 * ks;
                uint32_t a0[4], a1[4];
                {
                    int row = wm * 32 + l7 + 8 * qA_r;
                    ldm4(a0[0], a0[1], a0[2], a0[3], sb + SM_A + tile_off(row,      ch + qA_c));
                    ldm4(a1[0], a1[1], a1[2], a1[3], sb + SM_A + tile_off(row + 16, ch + qA_c));
                }
                uint32_t bf[2][4];
                #pragma unroll
                for (int np = 0; np < 2; ++np) {
                    int row = wn * 32 + np * 16 + l7 + 8 * qB_r;
                    ldm4(bf[np][0], bf[np][1], bf[np][2], bf[np][3],
                         bsm + tile_off(row, ch + qB_c));
                }
                #pragma unroll
                for (int np = 0; np < 2; ++np)
                    #pragma unroll
                    for (int sub = 0; sub < 2; ++sub) {
                        mma_bf16(acc[0][2 * np + sub], a0, bf[np][2 * sub], bf[np][2 * sub + 1]);
                        mma_bf16(acc[1][2 * np + sub], a1, bf[np][2 * sub], bf[np][2 * sub + 1]);
                    }
            }

            // this warp is done reading B[b]
            if (lane == 0) mbar_arrive(mb_empty[b]);
            ++n_empty[b];

            // epilogue (overlaps other warps' MMA phase)
            float col[8];
            #pragma unroll
            for (int k = 0; k < 8; ++k) col[k] = 0.f;
            #pragma unroll
            for (int ms = 0; ms < 2; ++ms)
                #pragma unroll
                for (int ns = 0; ns < 4; ++ns) {
                    float e0 = fexp2(acc[ms][ns][0]);
                    float e1 = fexp2(acc[ms][ns][1]);
                    float e2 = fexp2(acc[ms][ns][2]);
                    float e3 = fexp2(acc[ms][ns][3]);
                    rs[2 * ms]     += e0 + e1;
                    rs[2 * ms + 1] += e2 + e3;
                    col[2 * ns]     += e0 + e2;
                    col[2 * ns + 1] += e1 + e3;
                }
            if (!sym || jj != rb) {
                #pragma unroll
                for (int k = 0; k < 8; ++k) {
                    col[k] += __shfl_xor_sync(0xFFFFFFFFu, col[k], 4);
                    col[k] += __shfl_xor_sync(0xFFFFFFFFu, col[k], 8);
                    col[k] += __shfl_xor_sync(0xFFFFFFFFu, col[k], 16);
                }
                if (lane < 4) {
                    float* dst = &RSg[mcol][jj * MT + wn * 32];
                    #pragma unroll
                    for (int ns = 0; ns < 4; ++ns) {
                        atomicAdd(dst + ns * 8 + 2 * lane,     col[2 * ns]);
                        atomicAdd(dst + ns * 8 + 2 * lane + 1, col[2 * ns + 1]);
                    }
                }
            }

            // producer: refill this buffer with tile jj+2
            if (jj + 2 < jend) {
                mbar_wait(mb_empty[b], (uint32_t)((n_empty[b] - 1) & 1));
                load_tile(bsm, Y + (size_t)(jj + 2) * MT * DDIM, tid);
                cp_mbar_arrive_noinc(mb_full[b]);
                ++n_full[b];
            }
        }

        // flush row sums for this segment
        #pragma unroll
        for (int r = 0; r < 4; ++r) {
            rs[r] += __shfl_xor_sync(0xFFFFFFFFu, rs[r], 1);
            rs[r] += __shfl_xor_sync(0xFFFFFFFFu, rs[r], 2);
        }
        if (l3 == 0) {
            float* dst = &RSg[mrow][rb * MT + wm * 32];
            #pragma unroll
            for (int ms = 0; ms < 2; ++ms)
                #pragma unroll
                for (int cc = 0; cc < 2; ++cc)
                    atomicAdd(dst + ms * 16 + 8 * cc + g, rs[2 * ms + cc]);
        }

        // advance schedule state
        remaining -= seg;
        j = jend;
        if (j == NTILES) {
            ++rb;
            if (mat < 2) {
                if (rb == NTILES) { ++mat; rb = 0; j = 0; }
                else j = rb;
            } else {
                j = 0;
            }
        }
    }
}

// ---------------- Kernel 3: final reduction ----------------
__global__ void __launch_bounds__(256) reduce_kernel(float* out) {
    float s = 0.f;
    for (int i = threadIdx.x; i < NROWS; i += 256) {
        float den1 = RSg[0][i] + RSg[2][i] - exp2f(DGg[0][i]);
        float den2 = RSg[1][i] + RSg[3][i] - exp2f(DGg[1][i]);
        s += 0.5f * (__logf(den1) + __logf(den2)) - DGg[2][i] * LN2F;
    }
    #pragma unroll
    for (int o = 16; o; o >>= 1) s += __shfl_xor_sync(0xFFFFFFFFu, s, o);
    __shared__ float ws[8];
    if ((threadIdx.x & 31) == 0) ws[threadIdx.x >> 5] = s;
    __syncthreads();
    if (threadIdx.x < 8) {
        s = ws[threadIdx.x];
        #pragma unroll
        for (int o = 4; o; o >>= 1) s += __shfl_xor_sync(0xFFu, s, o);
        if (threadIdx.x == 0) out[0] = s / (float)NROWS;
    }
}

// ---------------- launch ----------------
extern "C" void kernel_launch(void* const* d_in, const int* in_sizes, int n_in,
                              void* d_out, int out_size) {
    const float* H1 = (const float*)d_in[0];
    const float* H2 = (const float*)d_in[1];
    float* out = (float*)d_out;

    norm_kernel<<<NROWS * 32 / 256, 256>>>(H1, H2);

    static bool attr_set = false;
    if (!attr_set) {
        cudaFuncSetAttribute(gram_kernel, cudaFuncAttributeMaxDynamicSharedMemorySize, SM_TOTAL);
        attr_set = true;
    }
    gram_kernel<<<NCTA, 512, SM_TOTAL>>>();

    reduce_kernel<<<1, 256>>>(out);
}

// round 9
// speedup vs baseline: 3.3426x; 1.0685x over previous
#include <cuda_runtime.h>
#include <cuda_bf16.h>
#include <cstdint>

#define DEVFN __device__ __forceinline__

constexpr int NROWS  = 8192;
constexpr int DDIM   = 256;
constexpr int MT     = 128;          // tile size (rows and cols)
constexpr int NTILES = NROWS / MT;   // 64 column tiles
constexpr int NCTA   = 148;
constexpr int NTHREADS = 256;        // 8 warps: 4 row-slices x 2 col-halves (32x64 warp tile)
constexpr int JOBS_SYM = NTILES * (NTILES + 1) / 2;          // 2080
constexpr int JOBS_ALL = 2 * JOBS_SYM + NTILES * NTILES;     // 8256
constexpr float SQRT_SCALE = 1.6986436005760748f;  // sqrt(2*log2(e)), tau=0.5
constexpr float LN2F = 0.6931471805599453f;

// Scratch (device globals; no runtime allocation allowed)
__device__ __align__(16) __nv_bfloat16 Z1g[NROWS * DDIM];
__device__ __align__(16) __nv_bfloat16 Z2g[NROWS * DDIM];
__device__ float RSg[4][NROWS];   // row sums of exp for S11, S22, S12, S21
__device__ float DGg[3][NROWS];   // log2-domain diagonals

// ---------------- helpers ----------------
DEVFN uint32_t smem_u32(const void* p) {
    return (uint32_t)__cvta_generic_to_shared(p);
}
DEVFN float fexp2(float x) {
    float y;
    asm("ex2.approx.ftz.f32 %0, %1;" : "=f"(y) : "f"(x));
    return y;
}
DEVFN void ldm4(uint32_t& r0, uint32_t& r1, uint32_t& r2, uint32_t& r3, uint32_t addr) {
    asm volatile("ldmatrix.sync.aligned.m8n8.x4.shared.b16 {%0,%1,%2,%3}, [%4];"
                 : "=r"(r0), "=r"(r1), "=r"(r2), "=r"(r3) : "r"(addr));
}
DEVFN void mma_bf16(float* c, const uint32_t* a, uint32_t b0, uint32_t b1) {
    asm volatile(
        "mma.sync.aligned.m16n8k16.row.col.f32.bf16.bf16.f32 "
        "{%0,%1,%2,%3}, {%4,%5,%6,%7}, {%8,%9}, {%0,%1,%2,%3};"
        : "+f"(c[0]), "+f"(c[1]), "+f"(c[2]), "+f"(c[3])
        : "r"(a[0]), "r"(a[1]), "r"(a[2]), "r"(a[3]), "r"(b0), "r"(b1));
}
// mbarrier primitives (sm_80/90 base features)
DEVFN void mbar_init(uint32_t mbar, uint32_t cnt) {
    asm volatile("mbarrier.init.shared.b64 [%0], %1;" :: "r"(mbar), "r"(cnt) : "memory");
}
DEVFN void mbar_arrive(uint32_t mbar) {
    asm volatile("mbarrier.arrive.shared.b64 _, [%0];" :: "r"(mbar) : "memory");
}
// .noinc: async arrival decrements the pending count that init accounted for.
DEVFN void cp_mbar_arrive_noinc(uint32_t mbar) {
    asm volatile("cp.async.mbarrier.arrive.noinc.shared.b64 [%0];" :: "r"(mbar) : "memory");
}
DEVFN void mbar_wait(uint32_t mbar, uint32_t parity) {
    asm volatile(
        "{\n\t.reg .pred P;\n"
        "MW_%=:\n\t"
        "mbarrier.try_wait.parity.shared.b64 P, [%0], %1;\n\t"
        "@!P bra MW_%=;\n\t}"
        :: "r"(mbar), "r"(parity) : "memory");
}

// ---------------- SMEM layout ----------------
constexpr int SM_MBAR  = 0;      // full0, full1, empty0, empty1 (8B each)
constexpr int SM_A     = 1024;
constexpr int SM_B0    = SM_A  + 65536;
constexpr int SM_B1    = SM_B0 + 65536;
constexpr int SM_TOTAL = SM_B1 + 65536;   // 197632 B

// swizzled byte offset of (row, 16B-chunk) within a 128x256 bf16 tile
DEVFN uint32_t tile_off(int row, int chunk) {
    return (uint32_t)(row * 512 + ((((chunk & 7) ^ (row & 7))) << 4) + ((chunk & 24) << 4));
}

// Load a 128x256 bf16 tile into swizzled SMEM via cp.async (16B chunks), 256 threads
DEVFN void load_tile(uint32_t sdst, const __nv_bfloat16* __restrict__ src, int tid) {
    #pragma unroll
    for (int it = 0; it < 16; ++it) {
        int idx = tid + it * 256;           // 4096 chunks total
        int row = idx >> 5;                 // 0..127
        int c   = idx & 31;                 // chunk within row
        const __nv_bfloat16* gp = src + ((size_t)row << 8) + (c << 3);
        asm volatile("cp.async.cg.shared.global [%0], [%1], 16;"
                     :: "r"(sdst + tile_off(row, c)), "l"(gp) : "memory");
    }
}

// ---------------- Kernel 1: normalize (pre-scaled) + diagonals + RS zero ----------------
__global__ void __launch_bounds__(256) norm_kernel(const float* __restrict__ H1,
                                                   const float* __restrict__ H2) {
    if (blockIdx.x < 128) ((float*)RSg)[blockIdx.x * 256 + threadIdx.x] = 0.f;

    int row  = (blockIdx.x * 256 + threadIdx.x) >> 5;   // one row per warp
    int lane = threadIdx.x & 31;
    const float4* p1 = (const float4*)(H1 + (size_t)row * DDIM);
    const float4* p2 = (const float4*)(H2 + (size_t)row * DDIM);
    float4 x0 = p1[lane], x1 = p1[lane + 32];
    float4 y0 = p2[lane], y1 = p2[lane + 32];

    float ss1 = x0.x*x0.x + x0.y*x0.y + x0.z*x0.z + x0.w*x0.w
              + x1.x*x1.x + x1.y*x1.y + x1.z*x1.z + x1.w*x1.w;
    float ss2 = y0.x*y0.x + y0.y*y0.y + y0.z*y0.z + y0.w*y0.w
              + y1.x*y1.x + y1.y*y1.y + y1.z*y1.z + y1.w*y1.w;
    #pragma unroll
    for (int o = 16; o; o >>= 1) {
        ss1 += __shfl_xor_sync(0xFFFFFFFFu, ss1, o);
        ss2 += __shfl_xor_sync(0xFFFFFFFFu, ss2, o);
    }
    float inv1 = SQRT_SCALE / fmaxf(sqrtf(ss1), 1e-12f);
    float inv2 = SQRT_SCALE / fmaxf(sqrtf(ss2), 1e-12f);

    __nv_bfloat162 z1p[4], z2p[4];
    z1p[0] = __float22bfloat162_rn(make_float2(x0.x * inv1, x0.y * inv1));
    z1p[1] = __float22bfloat162_rn(make_float2(x0.z * inv1, x0.w * inv1));
    z1p[2] = __float22bfloat162_rn(make_float2(x1.x * inv1, x1.y * inv1));
    z1p[3] = __float22bfloat162_rn(make_float2(x1.z * inv1, x1.w * inv1));
    z2p[0] = __float22bfloat162_rn(make_float2(y0.x * inv2, y0.y * inv2));
    z2p[1] = __float22bfloat162_rn(make_float2(y0.z * inv2, y0.w * inv2));
    z2p[2] = __float22bfloat162_rn(make_float2(y1.x * inv2, y1.y * inv2));
    z2p[3] = __float22bfloat162_rn(make_float2(y1.z * inv2, y1.w * inv2));

    uint32_t* z1 = (uint32_t*)(Z1g + (size_t)row * DDIM);
    uint32_t* z2 = (uint32_t*)(Z2g + (size_t)row * DDIM);
    z1[2 * lane]          = *(uint32_t*)&z1p[0];
    z1[2 * lane + 1]      = *(uint32_t*)&z1p[1];
    z1[64 + 2 * lane]     = *(uint32_t*)&z1p[2];
    z1[64 + 2 * lane + 1] = *(uint32_t*)&z1p[3];
    z2[2 * lane]          = *(uint32_t*)&z2p[0];
    z2[2 * lane + 1]      = *(uint32_t*)&z2p[1];
    z2[64 + 2 * lane]     = *(uint32_t*)&z2p[2];
    z2[64 + 2 * lane + 1] = *(uint32_t*)&z2p[3];

    float d11 = 0.f, d22 = 0.f, d12 = 0.f;
    #pragma unroll
    for (int k = 0; k < 4; ++k) {
        float2 f1 = __bfloat1622float2(z1p[k]);
        float2 f2 = __bfloat1622float2(z2p[k]);
        d11 += f1.x * f1.x + f1.y * f1.y;
        d22 += f2.x * f2.x + f2.y * f2.y;
        d12 += f1.x * f2.x + f1.y * f2.y;
    }
    #pragma unroll
    for (int o = 16; o; o >>= 1) {
        d11 += __shfl_xor_sync(0xFFFFFFFFu, d11, o);
        d22 += __shfl_xor_sync(0xFFFFFFFFu, d22, o);
        d12 += __shfl_xor_sync(0xFFFFFFFFu, d12, o);
    }
    if (lane == 0) {
        DGg[0][row] = d11;   // log2-domain diagonals
        DGg[1][row] = d22;
        DGg[2][row] = d12;
    }
}

// ---------------- Kernel 2: flat schedule + mbarrier pipeline, 32x64 warp tiles ----------
// 8 warps: wm = wid&3 (32-row slice), wn = wid>>2 (64-col half). Fragment SMEM traffic
// drops 25% vs 32x32 warp tiles (0.094 vs 0.125 B/MAC).
__global__ void __launch_bounds__(NTHREADS, 1) gram_kernel() {
    extern __shared__ char smem[];
    const uint32_t sb = smem_u32(smem);
    const int tid  = threadIdx.x;
    const int wid  = tid >> 5;
    const int lane = tid & 31;
    const int wm = wid & 3;
    const int wn = wid >> 2;
    const int bx = blockIdx.x;

    const uint32_t mb_full[2]  = { sb + SM_MBAR,      sb + SM_MBAR + 8 };
    const uint32_t mb_empty[2] = { sb + SM_MBAR + 16, sb + SM_MBAR + 24 };
    if (tid == 0) {
        mbar_init(mb_full[0], NTHREADS);
        mbar_init(mb_full[1], NTHREADS);
        mbar_init(mb_empty[0], 8);
        mbar_init(mb_empty[1], 8);
    }
    int n_full[2]  = {0, 0};
    int n_empty[2] = {0, 0};

    const int l7   = lane & 7;
    const int qA_r = (lane >> 3) & 1;
    const int qA_c = (lane >> 4);
    const int qB_r = (lane >> 4);
    const int qB_c = (lane >> 3) & 1;
    const int l3   = lane & 3;
    const int g    = lane >> 2;

    const int start = bx * JOBS_ALL / NCTA;
    const int end   = (bx + 1) * JOBS_ALL / NCTA;

    // decode start -> (mat, rb, j)
    int mat, rb, j;
    {
        int idx = start;
        if (idx < JOBS_SYM)          { mat = 0; }
        else if (idx < 2 * JOBS_SYM) { mat = 1; idx -= JOBS_SYM; }
        else                         { mat = 2; idx -= 2 * JOBS_SYM; }
        if (mat < 2) {
            rb = 0;
            while (idx >= NTILES - rb) { idx -= NTILES - rb; ++rb; }
            j = rb + idx;
        } else { rb = idx >> 6; j = idx & 63; }
    }

    int remaining = end - start;

    while (remaining > 0) {
        const __nv_bfloat16 *X, *Y;
        int mrow, mcol; bool sym;
        if (mat == 0)      { X = Z1g; Y = Z1g; mrow = 0; mcol = 0; sym = true; }
        else if (mat == 1) { X = Z2g; Y = Z2g; mrow = 1; mcol = 1; sym = true; }
        else               { X = Z1g; Y = Z2g; mrow = 2; mcol = 3; sym = false; }

        const int j0 = j;
        const int seg = min(remaining, NTILES - j0);
        const int jend = j0 + seg;

        __syncthreads();   // all warps done with previous segment's A/B; orders mbar init

        // prologue: A + first (up to) two B tiles
        load_tile(sb + SM_A, X + (size_t)rb * MT * DDIM, tid);
        {
            const int b0 = j0 & 1;
            load_tile(b0 ? sb + SM_B1 : sb + SM_B0, Y + (size_t)j0 * MT * DDIM, tid);
            cp_mbar_arrive_noinc(mb_full[b0]);
            ++n_full[b0];
            if (j0 + 1 < jend) {
                const int b1 = b0 ^ 1;
                load_tile(b1 ? sb + SM_B1 : sb + SM_B0, Y + (size_t)(j0 + 1) * MT * DDIM, tid);
                cp_mbar_arrive_noinc(mb_full[b1]);
                ++n_full[b1];
            }
        }

        float rs[4] = {0.f, 0.f, 0.f, 0.f};

        for (int jj = j0; jj < jend; ++jj) {
            const int b = jj & 1;
            const uint32_t bsm = b ? sb + SM_B1 : sb + SM_B0;

            mbar_wait(mb_full[b], (uint32_t)((n_full[b] - 1) & 1));

            float acc[2][8][4];
            #pragma unroll
            for (int ms = 0; ms < 2; ++ms)
                #pragma unroll
                for (int ns = 0; ns < 8; ++ns)
                    #pragma unroll
                    for (int c = 0; c < 4; ++c) acc[ms][ns][c] = 0.f;

            #pragma unroll
            for (int ks = 0; ks < 16; ++ks) {
                const int ch = 2 * ks;
                uint32_t a0[4], a1[4];
                {
                    int row = wm * 32 + l7 + 8 * qA_r;
                    ldm4(a0[0], a0[1], a0[2], a0[3], sb + SM_A + tile_off(row,      ch + qA_c));
                    ldm4(a1[0], a1[1], a1[2], a1[3], sb + SM_A + tile_off(row + 16, ch + qA_c));
                }
                uint32_t bf[4][4];
                #pragma unroll
                for (int np = 0; np < 4; ++np) {
                    int row = wn * 64 + np * 16 + l7 + 8 * qB_r;
                    ldm4(bf[np][0], bf[np][1], bf[np][2], bf[np][3],
                         bsm + tile_off(row, ch + qB_c));
                }
                #pragma unroll
                for (int np = 0; np < 4; ++np)
                    #pragma unroll
                    for (int sub = 0; sub < 2; ++sub) {
                        mma_bf16(acc[0][2 * np + sub], a0, bf[np][2 * sub], bf[np][2 * sub + 1]);
                        mma_bf16(acc[1][2 * np + sub], a1, bf[np][2 * sub], bf[np][2 * sub + 1]);
                    }
            }

            if (lane == 0) mbar_arrive(mb_empty[b]);
            ++n_empty[b];

            // epilogue (overlaps other warps' MMA phase)
            float col[16];
            #pragma unroll
            for (int k = 0; k < 16; ++k) col[k] = 0.f;
            #pragma unroll
            for (int ms = 0; ms < 2; ++ms)
                #pragma unroll
                for (int ns = 0; ns < 8; ++ns) {
                    float e0 = fexp2(acc[ms][ns][0]);
                    float e1 = fexp2(acc[ms][ns][1]);
                    float e2 = fexp2(acc[ms][ns][2]);
                    float e3 = fexp2(acc[ms][ns][3]);
                    rs[2 * ms]     += e0 + e1;
                    rs[2 * ms + 1] += e2 + e3;
                    col[2 * ns]     += e0 + e2;
                    col[2 * ns + 1] += e1 + e3;
                }
            if (!sym || jj != rb) {
                #pragma unroll
                for (int k = 0; k < 16; ++k) {
                    col[k] += __shfl_xor_sync(0xFFFFFFFFu, col[k], 4);
                    col[k] += __shfl_xor_sync(0xFFFFFFFFu, col[k], 8);
                    col[k] += __shfl_xor_sync(0xFFFFFFFFu, col[k], 16);
                }
                if (lane < 4) {
                    float* dst = &RSg[mcol][jj * MT + wn * 64];
                    #pragma unroll
                    for (int ns = 0; ns < 8; ++ns) {
                        atomicAdd(dst + ns * 8 + 2 * lane,     col[2 * ns]);
                        atomicAdd(dst + ns * 8 + 2 * lane + 1, col[2 * ns + 1]);
                    }
                }
            }

            // producer: refill this buffer with tile jj+2
            if (jj + 2 < jend) {
                mbar_wait(mb_empty[b], (uint32_t)((n_empty[b] - 1) & 1));
                load_tile(bsm, Y + (size_t)(jj + 2) * MT * DDIM, tid);
                cp_mbar_arrive_noinc(mb_full[b]);
                ++n_full[b];
            }
        }

        // flush row sums for this segment
        #pragma unroll
        for (int r = 0; r < 4; ++r) {
            rs[r] += __shfl_xor_sync(0xFFFFFFFFu, rs[r], 1);
            rs[r] += __shfl_xor_sync(0xFFFFFFFFu, rs[r], 2);
        }
        if (l3 == 0) {
            float* dst = &RSg[mrow][rb * MT + wm * 32];
            #pragma unroll
            for (int ms = 0; ms < 2; ++ms)
                #pragma unroll
                for (int cc = 0; cc < 2; ++cc)
                    atomicAdd(dst + ms * 16 + 8 * cc + g, rs[2 * ms + cc]);
        }

        // advance schedule state
        remaining -= seg;
        j = jend;
        if (j == NTILES) {
            ++rb;
            if (mat < 2) {
                if (rb == NTILES) { ++mat; rb = 0; j = 0; }
                else j = rb;
            } else {
                j = 0;
            }
        }
    }
}

// ---------------- Kernel 3: final reduction ----------------
__global__ void __launch_bounds__(256) reduce_kernel(float* out) {
    float s = 0.f;
    for (int i = threadIdx.x; i < NROWS; i += 256) {
        float den1 = RSg[0][i] + RSg[2][i] - exp2f(DGg[0][i]);
        float den2 = RSg[1][i] + RSg[3][i] - exp2f(DGg[1][i]);
        s += 0.5f * (__logf(den1) + __logf(den2)) - DGg[2][i] * LN2F;
    }
    #pragma unroll
    for (int o = 16; o; o >>= 1) s += __shfl_xor_sync(0xFFFFFFFFu, s, o);
    __shared__ float ws[8];
    if ((threadIdx.x & 31) == 0) ws[threadIdx.x >> 5] = s;
    __syncthreads();
    if (threadIdx.x < 8) {
        s = ws[threadIdx.x];
        #pragma unroll
        for (int o = 4; o; o >>= 1) s += __shfl_xor_sync(0xFFu, s, o);
        if (threadIdx.x == 0) out[0] = s / (float)NROWS;
    }
}

// ---------------- launch ----------------
extern "C" void kernel_launch(void* const* d_in, const int* in_sizes, int n_in,
                              void* d_out, int out_size) {
    const float* H1 = (const float*)d_in[0];
    const float* H2 = (const float*)d_in[1];
    float* out = (float*)d_out;

    norm_kernel<<<NROWS * 32 / 256, 256>>>(H1, H2);

    static bool attr_set = false;
    if (!attr_set) {
        cudaFuncSetAttribute(gram_kernel, cudaFuncAttributeMaxDynamicSharedMemorySize, SM_TOTAL);
        attr_set = true;
    }
    gram_kernel<<<NCTA, NTHREADS, SM_TOTAL>>>();

    reduce_kernel<<<1, 256>>>(out);
}